// round 14
// baseline (speedup 1.0000x reference)
#include <cuda_runtime.h>
#include <math.h>

#define N_NODES_MAX 100000
#define N_EDGES_MAX 1600000

typedef unsigned long long u64;
typedef ulonglong2 u64x2;

// -------- scratch (static __device__; no allocation at launch time) --------
__device__ float4 g_emb4[N_EDGES_MAX];     // (em0, em1, em2, unused)
__device__ float4 g_pos4[N_NODES_MAX];
__device__ float4 g_feat4[N_NODES_MAX];
__device__ float4 g_xA[N_NODES_MAX];
__device__ float4 g_xB[N_NODES_MAX];
__device__ float4 g_xC[N_NODES_MAX];

// -------- packed weights: staged in __device__, copied to __constant__ -----
struct __align__(16) CW {
    u64 w1[5][32];     // [pass][kp*4 + i], i<3 valid; pass: 0=conv1,1..3=core,4=conv3
    u64 c1[96];        // conv1 W2 [k*6 + jp], C1 folded
    u64 core[3][128];  // core W2 [p][k*8 + jp], CCORE folded
    u64 m[64];         // conv3 fused M [k*4 + u] = (M[k,u,0], M[k,u,1]), CCORE folded
};
__device__ CW g_stage;
__constant__ CW cw;

// -------- constants (all e3nn normalization folded) --------
#define EMBC  (1.14136f * 7.38905609893065f * 1.7320508075688772f)
#define C1    (1.41421356237f / 48.0f)
#define CCORE (1.41421356237f / (1.7320508075688772f * 32.0f))

// -------- packed f32x2 helpers --------
__device__ __forceinline__ u64 pack2(float x, float y) {
    u64 r; asm("mov.b64 %0, {%1, %2};" : "=l"(r) : "f"(x), "f"(y)); return r;
}
__device__ __forceinline__ void unpack2(u64 v, float& x, float& y) {
    asm("mov.b64 {%0, %1}, %2;" : "=f"(x), "=f"(y) : "l"(v));
}
__device__ __forceinline__ void fma2(u64& d, u64 a, u64 b) {
    asm("fma.rn.f32x2 %0, %1, %2, %0;" : "+l"(d) : "l"(a), "l"(b));
}
__device__ __forceinline__ u64 mul2(u64 a, u64 b) {
    u64 d; asm("mul.rn.f32x2 %0, %1, %2;" : "=l"(d) : "l"(a), "l"(b)); return d;
}

// -------- vectorized global reductions (sm_90+) --------
__device__ __forceinline__ void red_add_v4(float4* addr, float a, float b, float c, float d) {
    asm volatile("red.global.add.v4.f32 [%0], {%1, %2, %3, %4};"
                 :: "l"(addr), "f"(a), "f"(b), "f"(c), "f"(d) : "memory");
}
__device__ __forceinline__ void red_add_v2(float* addr, float a, float b) {
    asm volatile("red.global.add.v2.f32 [%0], {%1, %2};"
                 :: "l"(addr), "f"(a), "f"(b) : "memory");
}

// ============================================================================
// weight prep: pack/fold everything into g_stage (then memcpy'd to cw)
__global__ void wprep_kernel(
    const float* __restrict__ fc1_w1, const float* __restrict__ fc1_w2,
    const float* __restrict__ core_w1, const float* __restrict__ core_w2,
    const float* __restrict__ fc3_w1, const float* __restrict__ fc3_w2,
    const float* __restrict__ conv_w)
{
    int t = threadIdx.x;   // 128
    if (t < 32) {
        int kp = t >> 2, i = t & 3;
#pragma unroll
        for (int pp = 0; pp < 5; pp++) {
            const float* src = (pp == 0) ? fc1_w1 : (pp <= 3 ? core_w1 + (pp - 1) * 48 : fc3_w1);
            u64 v = 0ull;
            if (i < 3) v = pack2(src[i * 16 + 2 * kp], src[i * 16 + 2 * kp + 1]);
            g_stage.w1[pp][t] = v;
        }
    }
    if (t < 96) {
        int k = t / 6, jp = t % 6;
        g_stage.c1[t] = pack2(C1 * fc1_w2[k * 12 + 2 * jp], C1 * fc1_w2[k * 12 + 2 * jp + 1]);
    }
    {
        int k = t >> 3, jp = t & 7;
#pragma unroll
        for (int p = 0; p < 3; p++)
            g_stage.core[p][t] = pack2(CCORE * core_w2[p * 768 + k * 48 + 2 * jp],
                                       CCORE * core_w2[p * 768 + k * 48 + 2 * jp + 1]);
    }
    if (t < 64) {
        int k = t >> 2, u = t & 3;
        float s0 = 0.f, s1 = 0.f;
#pragma unroll
        for (int w = 0; w < 16; w++) {
            float f = fc3_w2[k * 64 + u * 16 + w];
            s0 += f * conv_w[w];
            s1 += f * conv_w[16 + w];
        }
        g_stage.m[t] = pack2(CCORE * s0, CCORE * s1);
    }
}

// ============================================================================
// prep: pack pos/feat into float4 tables, zero xA/xB, write bias into out
__global__ void __launch_bounds__(256) prep_kernel(
    const float* __restrict__ pos, const float* __restrict__ feat,
    const float* __restrict__ conv_b, float* __restrict__ out, int n)
{
    int i = blockIdx.x * 256 + threadIdx.x;
    if (i >= n) return;
    g_pos4[i]  = make_float4(pos[3 * i], pos[3 * i + 1], pos[3 * i + 2], 0.f);
    g_feat4[i] = make_float4(feat[3 * i], feat[3 * i + 1], feat[3 * i + 2], 0.f);
    g_xA[i] = make_float4(0.f, 0.f, 0.f, 0.f);
    g_xB[i] = make_float4(0.f, 0.f, 0.f, 0.f);
    ((float2*)out)[i] = make_float2(conv_b[0], conv_b[1]);
}

// r pair for two edges at slice kp from __constant__ W1 (LDC path, no L1):
#define R_PAIRS(W1P, kp)                                                        \
    u64x2 wi01 = *(const u64x2*)&(W1P)[(kp) * 4];                               \
    u64 wi2 = (W1P)[(kp) * 4 + 2];                                              \
    u64 vA = mul2(eA0, wi01.x); fma2(vA, eA1, wi01.y); fma2(vA, eA2, wi2);      \
    u64 vB = mul2(eB0, wi01.x); fma2(vB, eB1, wi01.y); fma2(vB, eB2, wi2);      \
    float a0, a1, b0, b1;                                                       \
    unpack2(vA, a0, a1); unpack2(vB, b0, b1);                                   \
    a0 = fmaxf(a0, 0.f); a1 = fmaxf(a1, 0.f);                                   \
    b0 = fmaxf(b0, 0.f); b1 = fmaxf(b1, 0.f);                                   \
    u64 raA = pack2(a0, a0), rbA = pack2(a1, a1);                               \
    u64 raB = pack2(b0, b0), rbB = pack2(b1, b1);

// ============================================================================
// conv1 body: 2 edges/thread, acc-form, constant weights; TAIL = guarded
template <bool TAIL>
__device__ __forceinline__ void conv1_body(
    const int* __restrict__ esrc, const int* __restrict__ edst,
    float4* __restrict__ xout, int base, int t, int E)
{
    int e0 = base + t, e1 = base + 128 + t;
    bool v0 = !TAIL || (e0 < E), v1 = !TAIL || (e1 < E);
    int s0 = 0, d0 = 0, s1 = 0, d1 = 0;
    if (v0) { s0 = esrc[e0]; d0 = edst[e0]; }
    if (v1) { s1 = esrc[e1]; d1 = edst[e1]; }

    float4 ps0 = g_pos4[s0], pd0 = g_pos4[d0], f0 = g_feat4[s0];
    float4 ps1 = g_pos4[s1], pd1 = g_pos4[d1], f1 = g_feat4[s1];

    float emA[3], emB[3];
    {
        float dx = pd0.x - ps0.x, dy = pd0.y - ps0.y, dz = pd0.z - ps0.z;
        float dist = sqrtf(dx * dx + dy * dy + dz * dz);
#pragma unroll
        for (int i = 0; i < 3; i++) {
            float tt = (dist - 0.75f * (float)(i + 1)) * (1.0f / 0.75f);
            float q = 1.0f - tt * tt;
            emA[i] = (q > 0.0f) ? EMBC * __expf(__fdividef(-2.0f, q)) : 0.0f;
        }
    }
    {
        float dx = pd1.x - ps1.x, dy = pd1.y - ps1.y, dz = pd1.z - ps1.z;
        float dist = sqrtf(dx * dx + dy * dy + dz * dz);
#pragma unroll
        for (int i = 0; i < 3; i++) {
            float tt = (dist - 0.75f * (float)(i + 1)) * (1.0f / 0.75f);
            float q = 1.0f - tt * tt;
            emB[i] = (q > 0.0f) ? EMBC * __expf(__fdividef(-2.0f, q)) : 0.0f;
        }
    }
    if (v0) g_emb4[e0] = make_float4(emA[0], emA[1], emA[2], 0.f);
    if (v1) g_emb4[e1] = make_float4(emB[0], emB[1], emB[2], 0.f);

    u64 eA0 = pack2(emA[0], emA[0]), eA1 = pack2(emA[1], emA[1]), eA2 = pack2(emA[2], emA[2]);
    u64 eB0 = pack2(emB[0], emB[0]), eB1 = pack2(emB[1], emB[1]), eB2 = pack2(emB[2], emB[2]);

    u64 accA[6], accB[6];
#pragma unroll
    for (int j = 0; j < 6; j++) { accA[j] = 0ull; accB[j] = 0ull; }

#pragma unroll
    for (int kp = 0; kp < 8; kp++) {
        R_PAIRS(cw.w1[0], kp)
        const u64x2* wr0 = (const u64x2*)&cw.c1[(2 * kp) * 6];
        const u64x2* wr1 = (const u64x2*)&cw.c1[(2 * kp + 1) * 6];
#pragma unroll
        for (int q = 0; q < 3; q++) {
            u64x2 w = wr0[q];
            fma2(accA[2 * q], raA, w.x); fma2(accA[2 * q + 1], raA, w.y);
            fma2(accB[2 * q], raB, w.x); fma2(accB[2 * q + 1], raB, w.y);
        }
#pragma unroll
        for (int q = 0; q < 3; q++) {
            u64x2 w = wr1[q];
            fma2(accA[2 * q], rbA, w.x); fma2(accA[2 * q + 1], rbA, w.y);
            fma2(accB[2 * q], rbB, w.x); fma2(accB[2 * q + 1], rbB, w.y);
        }
    }

    {
        u64 xu0 = pack2(f0.x, f0.x), xu1 = pack2(f0.y, f0.y), xu2 = pack2(f0.z, f0.z);
        u64 m01 = mul2(xu0, accA[0]), m23 = mul2(xu0, accA[1]);
        fma2(m01, xu1, accA[2]); fma2(m23, xu1, accA[3]);
        fma2(m01, xu2, accA[4]); fma2(m23, xu2, accA[5]);
        float m0, m1, m2, m3;
        unpack2(m01, m0, m1); unpack2(m23, m2, m3);
        if (v0) red_add_v4(&xout[d0], m0, m1, m2, m3);
    }
    {
        u64 xu0 = pack2(f1.x, f1.x), xu1 = pack2(f1.y, f1.y), xu2 = pack2(f1.z, f1.z);
        u64 m01 = mul2(xu0, accB[0]), m23 = mul2(xu0, accB[1]);
        fma2(m01, xu1, accB[2]); fma2(m23, xu1, accB[3]);
        fma2(m01, xu2, accB[4]); fma2(m23, xu2, accB[5]);
        float m0, m1, m2, m3;
        unpack2(m01, m0, m1); unpack2(m23, m2, m3);
        if (v1) red_add_v4(&xout[d1], m0, m1, m2, m3);
    }
}

__global__ void __launch_bounds__(128, 7) conv1_kernel(
    const int* __restrict__ esrc, const int* __restrict__ edst,
    float4* __restrict__ xout, int E)
{
    int t = threadIdx.x;
    int base = blockIdx.x * 256;
    if (base + 256 <= E) conv1_body<false>(esrc, edst, xout, base, t, E);
    else                 conv1_body<true >(esrc, edst, xout, base, t, E);
}

// ============================================================================
// core body: 2 edges/thread, acc-form, constant weights; TAIL = guarded
template <bool TAIL>
__device__ __forceinline__ void core_body(
    const int* __restrict__ esrc, const int* __restrict__ edst, int p,
    const float4* __restrict__ xin, float4* __restrict__ xout,
    int base, int t, int E)
{
    int e0 = base + t, e1 = base + 128 + t;
    bool v0 = !TAIL || (e0 < E), v1 = !TAIL || (e1 < E);
    int s0 = 0, d0 = 0, s1 = 0, d1 = 0;
    if (v0) { s0 = esrc[e0]; d0 = edst[e0]; }
    if (v1) { s1 = esrc[e1]; d1 = edst[e1]; }

    float4 x0 = xin[s0];
    float4 x1 = xin[s1];
    float4 emA = g_emb4[TAIL ? (v0 ? e0 : 0) : e0];
    float4 emB = g_emb4[TAIL ? (v1 ? e1 : 0) : e1];

    int wp = 1 + p;
    u64 eA0 = pack2(emA.x, emA.x), eA1 = pack2(emA.y, emA.y), eA2 = pack2(emA.z, emA.z);
    u64 eB0 = pack2(emB.x, emB.x), eB1 = pack2(emB.y, emB.y), eB2 = pack2(emB.z, emB.z);

    u64 accA[8], accB[8];
#pragma unroll
    for (int j = 0; j < 8; j++) { accA[j] = 0ull; accB[j] = 0ull; }

#pragma unroll
    for (int kp = 0; kp < 8; kp++) {
        R_PAIRS(cw.w1[wp], kp)
        const u64x2* wr0 = (const u64x2*)&cw.core[p][(2 * kp) * 8];
        const u64x2* wr1 = (const u64x2*)&cw.core[p][(2 * kp + 1) * 8];
#pragma unroll
        for (int q = 0; q < 4; q++) {
            u64x2 w = wr0[q];
            fma2(accA[2 * q], raA, w.x); fma2(accA[2 * q + 1], raA, w.y);
            fma2(accB[2 * q], raB, w.x); fma2(accB[2 * q + 1], raB, w.y);
        }
#pragma unroll
        for (int q = 0; q < 4; q++) {
            u64x2 w = wr1[q];
            fma2(accA[2 * q], rbA, w.x); fma2(accA[2 * q + 1], rbA, w.y);
            fma2(accB[2 * q], rbB, w.x); fma2(accB[2 * q + 1], rbB, w.y);
        }
    }

    {
        u64 xu0 = pack2(x0.x, x0.x), xu1 = pack2(x0.y, x0.y);
        u64 xu2 = pack2(x0.z, x0.z), xu3 = pack2(x0.w, x0.w);
        u64 m01 = mul2(xu0, accA[0]), m23 = mul2(xu0, accA[1]);
        fma2(m01, xu1, accA[2]); fma2(m23, xu1, accA[3]);
        fma2(m01, xu2, accA[4]); fma2(m23, xu2, accA[5]);
        fma2(m01, xu3, accA[6]); fma2(m23, xu3, accA[7]);
        float m0, m1, m2, m3;
        unpack2(m01, m0, m1); unpack2(m23, m2, m3);
        if (v0) red_add_v4(&xout[d0], m0, m1, m2, m3);
    }
    {
        u64 xu0 = pack2(x1.x, x1.x), xu1 = pack2(x1.y, x1.y);
        u64 xu2 = pack2(x1.z, x1.z), xu3 = pack2(x1.w, x1.w);
        u64 m01 = mul2(xu0, accB[0]), m23 = mul2(xu0, accB[1]);
        fma2(m01, xu1, accB[2]); fma2(m23, xu1, accB[3]);
        fma2(m01, xu2, accB[4]); fma2(m23, xu2, accB[5]);
        fma2(m01, xu3, accB[6]); fma2(m23, xu3, accB[7]);
        float m0, m1, m2, m3;
        unpack2(m01, m0, m1); unpack2(m23, m2, m3);
        if (v1) red_add_v4(&xout[d1], m0, m1, m2, m3);
    }
}

__global__ void __launch_bounds__(128, 8) core_kernel(
    const int* __restrict__ esrc, const int* __restrict__ edst, int p,
    const float4* __restrict__ xin, float4* __restrict__ xout,
    float4* __restrict__ zbuf, int zn, int E)
{
    int t = threadIdx.x;
    int zi = blockIdx.x * 128 + t;
    if (zi < zn) zbuf[zi] = make_float4(0.f, 0.f, 0.f, 0.f);

    int base = blockIdx.x * 256;
    if (base + 256 <= E) core_body<false>(esrc, edst, p, xin, xout, base, t, E);
    else                 core_body<true >(esrc, edst, p, xin, xout, base, t, E);
}

// ============================================================================
// conv3 body: fused Conv1d(16,2,1), 2 edges/thread, acc-form, const weights
template <bool TAIL>
__device__ __forceinline__ void conv3_body(
    const int* __restrict__ esrc, const int* __restrict__ edst,
    const float4* __restrict__ xin, float* __restrict__ out,
    int base, int t, int E)
{
    int e0 = base + t, e1 = base + 128 + t;
    bool v0 = !TAIL || (e0 < E), v1 = !TAIL || (e1 < E);
    int s0 = 0, d0 = 0, s1 = 0, d1 = 0;
    if (v0) { s0 = esrc[e0]; d0 = edst[e0]; }
    if (v1) { s1 = esrc[e1]; d1 = edst[e1]; }

    float4 x0 = xin[s0];
    float4 x1 = xin[s1];
    float4 emA = g_emb4[TAIL ? (v0 ? e0 : 0) : e0];
    float4 emB = g_emb4[TAIL ? (v1 ? e1 : 0) : e1];

    u64 eA0 = pack2(emA.x, emA.x), eA1 = pack2(emA.y, emA.y), eA2 = pack2(emA.z, emA.z);
    u64 eB0 = pack2(emB.x, emB.x), eB1 = pack2(emB.y, emB.y), eB2 = pack2(emB.z, emB.z);

    u64 accA[4], accB[4];
#pragma unroll
    for (int j = 0; j < 4; j++) { accA[j] = 0ull; accB[j] = 0ull; }

#pragma unroll
    for (int kp = 0; kp < 8; kp++) {
        R_PAIRS(cw.w1[4], kp)
        const u64x2* wr0 = (const u64x2*)&cw.m[(2 * kp) * 4];
        const u64x2* wr1 = (const u64x2*)&cw.m[(2 * kp + 1) * 4];
#pragma unroll
        for (int q = 0; q < 2; q++) {
            u64x2 w = wr0[q];
            fma2(accA[2 * q], raA, w.x); fma2(accA[2 * q + 1], raA, w.y);
            fma2(accB[2 * q], raB, w.x); fma2(accB[2 * q + 1], raB, w.y);
        }
#pragma unroll
        for (int q = 0; q < 2; q++) {
            u64x2 w = wr1[q];
            fma2(accA[2 * q], rbA, w.x); fma2(accA[2 * q + 1], rbA, w.y);
            fma2(accB[2 * q], rbB, w.x); fma2(accB[2 * q + 1], rbB, w.y);
        }
    }

    {
        u64 xu0 = pack2(x0.x, x0.x), xu1 = pack2(x0.y, x0.y);
        u64 xu2 = pack2(x0.z, x0.z), xu3 = pack2(x0.w, x0.w);
        u64 mc = mul2(xu0, accA[0]);
        fma2(mc, xu1, accA[1]); fma2(mc, xu2, accA[2]); fma2(mc, xu3, accA[3]);
        float m0, m1;
        unpack2(mc, m0, m1);
        if (v0) red_add_v2(out + 2 * d0, m0, m1);
    }
    {
        u64 xu0 = pack2(x1.x, x1.x), xu1 = pack2(x1.y, x1.y);
        u64 xu2 = pack2(x1.z, x1.z), xu3 = pack2(x1.w, x1.w);
        u64 mc = mul2(xu0, accB[0]);
        fma2(mc, xu1, accB[1]); fma2(mc, xu2, accB[2]); fma2(mc, xu3, accB[3]);
        float m0, m1;
        unpack2(mc, m0, m1);
        if (v1) red_add_v2(out + 2 * d1, m0, m1);
    }
}

__global__ void __launch_bounds__(128, 8) conv3_kernel(
    const int* __restrict__ esrc, const int* __restrict__ edst,
    const float4* __restrict__ xin, float* __restrict__ out, int E)
{
    int t = threadIdx.x;
    int base = blockIdx.x * 256;
    if (base + 256 <= E) conv3_body<false>(esrc, edst, xin, out, base, t, E);
    else                 conv3_body<true >(esrc, edst, xin, out, base, t, E);
}

// ============================================================================
extern "C" void kernel_launch(void* const* d_in, const int* in_sizes, int n_in,
                              void* d_out, int out_size)
{
    const float* pos     = (const float*)d_in[0];
    const float* feat    = (const float*)d_in[1];
    const int*   esrc    = (const int*)  d_in[2];
    const int*   edst    = (const int*)  d_in[3];
    const float* fc1_w1  = (const float*)d_in[4];
    const float* fc1_w2  = (const float*)d_in[5];
    const float* core_w1 = (const float*)d_in[6];   // [3,3,16]
    const float* core_w2 = (const float*)d_in[7];   // [3,16,48]
    const float* fc3_w1  = (const float*)d_in[8];
    const float* fc3_w2  = (const float*)d_in[9];
    const float* conv_w  = (const float*)d_in[10];
    const float* conv_b  = (const float*)d_in[11];
    float* out = (float*)d_out;

    int E = in_sizes[2];
    int n = in_sizes[0] / 3;

    float4 *xA, *xB, *xC;
    void* stg;
    cudaGetSymbolAddress((void**)&xA, g_xA);
    cudaGetSymbolAddress((void**)&xB, g_xB);
    cudaGetSymbolAddress((void**)&xC, g_xC);
    cudaGetSymbolAddress(&stg, g_stage);

    int eb = (E + 255) / 256;   // 256 edges per 128-thread block
    int nb = (n + 255) / 256;

    // pack + fold weights, then stage them into the constant bank (D2D, graph-legal)
    wprep_kernel<<<1, 128>>>(fc1_w1, fc1_w2, core_w1, core_w2, fc3_w1, fc3_w2, conv_w);
    cudaMemcpyToSymbolAsync(cw, stg, sizeof(CW), 0, cudaMemcpyDeviceToDevice, 0);

    prep_kernel<<<nb, 256>>>(pos, feat, conv_b, out, n);

    conv1_kernel<<<eb, 128>>>(esrc, edst, xA, E);
    // core1: A->B, zero C for core2's output
    core_kernel<<<eb, 128>>>(esrc, edst, 0, xA, xB, xC, n, E);
    // core2: B->C, zero A for core3's output
    core_kernel<<<eb, 128>>>(esrc, edst, 1, xB, xC, xA, n, E);
    // core3: C->A
    core_kernel<<<eb, 128>>>(esrc, edst, 2, xC, xA, (float4*)0, 0, E);

    conv3_kernel<<<eb, 128>>>(esrc, edst, xA, out, E);
}

// round 16
// speedup vs baseline: 1.5525x; 1.5525x over previous
#include <cuda_runtime.h>
#include <math.h>

#define N_NODES_MAX 100000
#define N_EDGES_MAX 1600000

typedef unsigned long long u64;
typedef ulonglong2 u64x2;

// -------- scratch (static __device__; no allocation at launch time) --------
__device__ float4 g_emb4[N_EDGES_MAX];     // (em0, em1, em2, unused)
__device__ float4 g_pos4[N_NODES_MAX];
__device__ float4 g_feat4[N_NODES_MAX];
__device__ float4 g_xA[N_NODES_MAX];
__device__ float4 g_xB[N_NODES_MAX];
__device__ float4 g_xC[N_NODES_MAX];

// -------- packed weights: staged in __device__, copied to __constant__ -----
struct __align__(16) CW {
    u64 w1[5][32];     // [pass][kp*4 + i], i<3 valid; pass: 0=conv1,1..3=core,4=conv3
    u64 c1[96];        // conv1 W2 [k*6 + jp], C1 folded
    u64 core[3][128];  // core W2 [p][k*8 + jp], CCORE folded
    u64 m[64];         // conv3 fused M [k*4 + u] = (M[k,u,0], M[k,u,1]), CCORE folded
};
__device__ CW g_stage;
__constant__ CW cw;

// -------- constants (all e3nn normalization folded) --------
#define EMBC  (1.14136f * 7.38905609893065f * 1.7320508075688772f)
#define C1    (1.41421356237f / 48.0f)
#define CCORE (1.41421356237f / (1.7320508075688772f * 32.0f))

// -------- packed f32x2 helpers --------
__device__ __forceinline__ u64 pack2(float x, float y) {
    u64 r; asm("mov.b64 %0, {%1, %2};" : "=l"(r) : "f"(x), "f"(y)); return r;
}
__device__ __forceinline__ void unpack2(u64 v, float& x, float& y) {
    asm("mov.b64 {%0, %1}, %2;" : "=f"(x), "=f"(y) : "l"(v));
}
__device__ __forceinline__ void fma2(u64& d, u64 a, u64 b) {
    asm("fma.rn.f32x2 %0, %1, %2, %0;" : "+l"(d) : "l"(a), "l"(b));
}
__device__ __forceinline__ u64 mul2(u64 a, u64 b) {
    u64 d; asm("mul.rn.f32x2 %0, %1, %2;" : "=l"(d) : "l"(a), "l"(b)); return d;
}

// -------- vectorized global reductions (sm_90+) --------
__device__ __forceinline__ void red_add_v4(float4* addr, float a, float b, float c, float d) {
    asm volatile("red.global.add.v4.f32 [%0], {%1, %2, %3, %4};"
                 :: "l"(addr), "f"(a), "f"(b), "f"(c), "f"(d) : "memory");
}
__device__ __forceinline__ void red_add_v2(float* addr, float a, float b) {
    asm volatile("red.global.add.v2.f32 [%0], {%1, %2};"
                 :: "l"(addr), "f"(a), "f"(b) : "memory");
}

// ============================================================================
// weight prep: pack/fold everything into g_stage (then memcpy'd to cw)
__global__ void wprep_kernel(
    const float* __restrict__ fc1_w1, const float* __restrict__ fc1_w2,
    const float* __restrict__ core_w1, const float* __restrict__ core_w2,
    const float* __restrict__ fc3_w1, const float* __restrict__ fc3_w2,
    const float* __restrict__ conv_w)
{
    int t = threadIdx.x;   // 128
    if (t < 32) {
        int kp = t >> 2, i = t & 3;
#pragma unroll
        for (int pp = 0; pp < 5; pp++) {
            const float* src = (pp == 0) ? fc1_w1 : (pp <= 3 ? core_w1 + (pp - 1) * 48 : fc3_w1);
            u64 v = 0ull;
            if (i < 3) v = pack2(src[i * 16 + 2 * kp], src[i * 16 + 2 * kp + 1]);
            g_stage.w1[pp][t] = v;
        }
    }
    if (t < 96) {
        int k = t / 6, jp = t % 6;
        g_stage.c1[t] = pack2(C1 * fc1_w2[k * 12 + 2 * jp], C1 * fc1_w2[k * 12 + 2 * jp + 1]);
    }
    {
        int k = t >> 3, jp = t & 7;
#pragma unroll
        for (int p = 0; p < 3; p++)
            g_stage.core[p][t] = pack2(CCORE * core_w2[p * 768 + k * 48 + 2 * jp],
                                       CCORE * core_w2[p * 768 + k * 48 + 2 * jp + 1]);
    }
    if (t < 64) {
        int k = t >> 2, u = t & 3;
        float s0 = 0.f, s1 = 0.f;
#pragma unroll
        for (int w = 0; w < 16; w++) {
            float f = fc3_w2[k * 64 + u * 16 + w];
            s0 += f * conv_w[w];
            s1 += f * conv_w[16 + w];
        }
        g_stage.m[t] = pack2(CCORE * s0, CCORE * s1);
    }
}

// ============================================================================
// prep: pack pos/feat into float4 tables, zero xA/xB, write bias into out
__global__ void __launch_bounds__(256) prep_kernel(
    const float* __restrict__ pos, const float* __restrict__ feat,
    const float* __restrict__ conv_b, float* __restrict__ out, int n)
{
    int i = blockIdx.x * 256 + threadIdx.x;
    if (i >= n) return;
    g_pos4[i]  = make_float4(pos[3 * i], pos[3 * i + 1], pos[3 * i + 2], 0.f);
    g_feat4[i] = make_float4(feat[3 * i], feat[3 * i + 1], feat[3 * i + 2], 0.f);
    g_xA[i] = make_float4(0.f, 0.f, 0.f, 0.f);
    g_xB[i] = make_float4(0.f, 0.f, 0.f, 0.f);
    ((float2*)out)[i] = make_float2(conv_b[0], conv_b[1]);
}

// r pair for two edges at slice kp from __constant__ W1 (LDC path, no L1):
#define R_PAIRS(W1P, kp)                                                        \
    u64x2 wi01 = *(const u64x2*)&(W1P)[(kp) * 4];                               \
    u64 wi2 = (W1P)[(kp) * 4 + 2];                                              \
    u64 vA = mul2(eA0, wi01.x); fma2(vA, eA1, wi01.y); fma2(vA, eA2, wi2);      \
    u64 vB = mul2(eB0, wi01.x); fma2(vB, eB1, wi01.y); fma2(vB, eB2, wi2);      \
    float a0, a1, b0, b1;                                                       \
    unpack2(vA, a0, a1); unpack2(vB, b0, b1);                                   \
    a0 = fmaxf(a0, 0.f); a1 = fmaxf(a1, 0.f);                                   \
    b0 = fmaxf(b0, 0.f); b1 = fmaxf(b1, 0.f);                                   \
    u64 raA = pack2(a0, a0), rbA = pack2(a1, a1);                               \
    u64 raB = pack2(b0, b0), rbB = pack2(b1, b1);

// ============================================================================
// conv1 body: 2 edges/thread, acc-form, constant weights; TAIL = guarded
template <bool TAIL>
__device__ __forceinline__ void conv1_body(
    const int* __restrict__ esrc, const int* __restrict__ edst,
    float4* __restrict__ xout, int base, int t, int E)
{
    int e0 = base + t, e1 = base + 128 + t;
    bool v0 = !TAIL || (e0 < E), v1 = !TAIL || (e1 < E);
    int s0 = 0, d0 = 0, s1 = 0, d1 = 0;
    if (v0) { s0 = esrc[e0]; d0 = edst[e0]; }
    if (v1) { s1 = esrc[e1]; d1 = edst[e1]; }

    float4 ps0 = g_pos4[s0], pd0 = g_pos4[d0], f0 = g_feat4[s0];
    float4 ps1 = g_pos4[s1], pd1 = g_pos4[d1], f1 = g_feat4[s1];

    float emA[3], emB[3];
    {
        float dx = pd0.x - ps0.x, dy = pd0.y - ps0.y, dz = pd0.z - ps0.z;
        float dist = sqrtf(dx * dx + dy * dy + dz * dz);
#pragma unroll
        for (int i = 0; i < 3; i++) {
            float tt = (dist - 0.75f * (float)(i + 1)) * (1.0f / 0.75f);
            float q = 1.0f - tt * tt;
            emA[i] = (q > 0.0f) ? EMBC * __expf(__fdividef(-2.0f, q)) : 0.0f;
        }
    }
    {
        float dx = pd1.x - ps1.x, dy = pd1.y - ps1.y, dz = pd1.z - ps1.z;
        float dist = sqrtf(dx * dx + dy * dy + dz * dz);
#pragma unroll
        for (int i = 0; i < 3; i++) {
            float tt = (dist - 0.75f * (float)(i + 1)) * (1.0f / 0.75f);
            float q = 1.0f - tt * tt;
            emB[i] = (q > 0.0f) ? EMBC * __expf(__fdividef(-2.0f, q)) : 0.0f;
        }
    }
    if (v0) g_emb4[e0] = make_float4(emA[0], emA[1], emA[2], 0.f);
    if (v1) g_emb4[e1] = make_float4(emB[0], emB[1], emB[2], 0.f);

    u64 eA0 = pack2(emA[0], emA[0]), eA1 = pack2(emA[1], emA[1]), eA2 = pack2(emA[2], emA[2]);
    u64 eB0 = pack2(emB[0], emB[0]), eB1 = pack2(emB[1], emB[1]), eB2 = pack2(emB[2], emB[2]);

    u64 accA[6], accB[6];
#pragma unroll
    for (int j = 0; j < 6; j++) { accA[j] = 0ull; accB[j] = 0ull; }

#pragma unroll
    for (int kp = 0; kp < 8; kp++) {
        R_PAIRS(cw.w1[0], kp)
        const u64x2* wr0 = (const u64x2*)&cw.c1[(2 * kp) * 6];
        const u64x2* wr1 = (const u64x2*)&cw.c1[(2 * kp + 1) * 6];
#pragma unroll
        for (int q = 0; q < 3; q++) {
            u64x2 w = wr0[q];
            fma2(accA[2 * q], raA, w.x); fma2(accA[2 * q + 1], raA, w.y);
            fma2(accB[2 * q], raB, w.x); fma2(accB[2 * q + 1], raB, w.y);
        }
#pragma unroll
        for (int q = 0; q < 3; q++) {
            u64x2 w = wr1[q];
            fma2(accA[2 * q], rbA, w.x); fma2(accA[2 * q + 1], rbA, w.y);
            fma2(accB[2 * q], rbB, w.x); fma2(accB[2 * q + 1], rbB, w.y);
        }
    }

    {
        u64 xu0 = pack2(f0.x, f0.x), xu1 = pack2(f0.y, f0.y), xu2 = pack2(f0.z, f0.z);
        u64 m01 = mul2(xu0, accA[0]), m23 = mul2(xu0, accA[1]);
        fma2(m01, xu1, accA[2]); fma2(m23, xu1, accA[3]);
        fma2(m01, xu2, accA[4]); fma2(m23, xu2, accA[5]);
        float m0, m1, m2, m3;
        unpack2(m01, m0, m1); unpack2(m23, m2, m3);
        if (v0) red_add_v4(&xout[d0], m0, m1, m2, m3);
    }
    {
        u64 xu0 = pack2(f1.x, f1.x), xu1 = pack2(f1.y, f1.y), xu2 = pack2(f1.z, f1.z);
        u64 m01 = mul2(xu0, accB[0]), m23 = mul2(xu0, accB[1]);
        fma2(m01, xu1, accB[2]); fma2(m23, xu1, accB[3]);
        fma2(m01, xu2, accB[4]); fma2(m23, xu2, accB[5]);
        float m0, m1, m2, m3;
        unpack2(m01, m0, m1); unpack2(m23, m2, m3);
        if (v1) red_add_v4(&xout[d1], m0, m1, m2, m3);
    }
}

__global__ void __launch_bounds__(128, 7) conv1_kernel(
    const int* __restrict__ esrc, const int* __restrict__ edst,
    float4* __restrict__ xout, int E)
{
    int t = threadIdx.x;
    int base = blockIdx.x * 256;
    if (base + 256 <= E) conv1_body<false>(esrc, edst, xout, base, t, E);
    else                 conv1_body<true >(esrc, edst, xout, base, t, E);
}

// ============================================================================
// core body: 2 edges/thread, acc-form, constant weights; TAIL = guarded
template <bool TAIL>
__device__ __forceinline__ void core_body(
    const int* __restrict__ esrc, const int* __restrict__ edst, int p,
    const float4* __restrict__ xin, float4* __restrict__ xout,
    int base, int t, int E)
{
    int e0 = base + t, e1 = base + 128 + t;
    bool v0 = !TAIL || (e0 < E), v1 = !TAIL || (e1 < E);
    int s0 = 0, d0 = 0, s1 = 0, d1 = 0;
    if (v0) { s0 = esrc[e0]; d0 = edst[e0]; }
    if (v1) { s1 = esrc[e1]; d1 = edst[e1]; }

    float4 x0 = xin[s0];
    float4 x1 = xin[s1];
    float4 emA = g_emb4[TAIL ? (v0 ? e0 : 0) : e0];
    float4 emB = g_emb4[TAIL ? (v1 ? e1 : 0) : e1];

    int wp = 1 + p;
    u64 eA0 = pack2(emA.x, emA.x), eA1 = pack2(emA.y, emA.y), eA2 = pack2(emA.z, emA.z);
    u64 eB0 = pack2(emB.x, emB.x), eB1 = pack2(emB.y, emB.y), eB2 = pack2(emB.z, emB.z);

    u64 accA[8], accB[8];
#pragma unroll
    for (int j = 0; j < 8; j++) { accA[j] = 0ull; accB[j] = 0ull; }

#pragma unroll
    for (int kp = 0; kp < 8; kp++) {
        R_PAIRS(cw.w1[wp], kp)
        const u64x2* wr0 = (const u64x2*)&cw.core[p][(2 * kp) * 8];
        const u64x2* wr1 = (const u64x2*)&cw.core[p][(2 * kp + 1) * 8];
#pragma unroll
        for (int q = 0; q < 4; q++) {
            u64x2 w = wr0[q];
            fma2(accA[2 * q], raA, w.x); fma2(accA[2 * q + 1], raA, w.y);
            fma2(accB[2 * q], raB, w.x); fma2(accB[2 * q + 1], raB, w.y);
        }
#pragma unroll
        for (int q = 0; q < 4; q++) {
            u64x2 w = wr1[q];
            fma2(accA[2 * q], rbA, w.x); fma2(accA[2 * q + 1], rbA, w.y);
            fma2(accB[2 * q], rbB, w.x); fma2(accB[2 * q + 1], rbB, w.y);
        }
    }

    {
        u64 xu0 = pack2(x0.x, x0.x), xu1 = pack2(x0.y, x0.y);
        u64 xu2 = pack2(x0.z, x0.z), xu3 = pack2(x0.w, x0.w);
        u64 m01 = mul2(xu0, accA[0]), m23 = mul2(xu0, accA[1]);
        fma2(m01, xu1, accA[2]); fma2(m23, xu1, accA[3]);
        fma2(m01, xu2, accA[4]); fma2(m23, xu2, accA[5]);
        fma2(m01, xu3, accA[6]); fma2(m23, xu3, accA[7]);
        float m0, m1, m2, m3;
        unpack2(m01, m0, m1); unpack2(m23, m2, m3);
        if (v0) red_add_v4(&xout[d0], m0, m1, m2, m3);
    }
    {
        u64 xu0 = pack2(x1.x, x1.x), xu1 = pack2(x1.y, x1.y);
        u64 xu2 = pack2(x1.z, x1.z), xu3 = pack2(x1.w, x1.w);
        u64 m01 = mul2(xu0, accB[0]), m23 = mul2(xu0, accB[1]);
        fma2(m01, xu1, accB[2]); fma2(m23, xu1, accB[3]);
        fma2(m01, xu2, accB[4]); fma2(m23, xu2, accB[5]);
        fma2(m01, xu3, accB[6]); fma2(m23, xu3, accB[7]);
        float m0, m1, m2, m3;
        unpack2(m01, m0, m1); unpack2(m23, m2, m3);
        if (v1) red_add_v4(&xout[d1], m0, m1, m2, m3);
    }
}

__global__ void __launch_bounds__(128, 7) core_kernel(
    const int* __restrict__ esrc, const int* __restrict__ edst, int p,
    const float4* __restrict__ xin, float4* __restrict__ xout,
    float4* __restrict__ zbuf, int zn, int E)
{
    int t = threadIdx.x;
    int zi = blockIdx.x * 128 + t;
    if (zi < zn) zbuf[zi] = make_float4(0.f, 0.f, 0.f, 0.f);

    int base = blockIdx.x * 256;
    if (base + 256 <= E) core_body<false>(esrc, edst, p, xin, xout, base, t, E);
    else                 core_body<true >(esrc, edst, p, xin, xout, base, t, E);
}

// ============================================================================
// conv3 body: fused Conv1d(16,2,1), 2 edges/thread, acc-form, const weights
template <bool TAIL>
__device__ __forceinline__ void conv3_body(
    const int* __restrict__ esrc, const int* __restrict__ edst,
    const float4* __restrict__ xin, float* __restrict__ out,
    int base, int t, int E)
{
    int e0 = base + t, e1 = base + 128 + t;
    bool v0 = !TAIL || (e0 < E), v1 = !TAIL || (e1 < E);
    int s0 = 0, d0 = 0, s1 = 0, d1 = 0;
    if (v0) { s0 = esrc[e0]; d0 = edst[e0]; }
    if (v1) { s1 = esrc[e1]; d1 = edst[e1]; }

    float4 x0 = xin[s0];
    float4 x1 = xin[s1];
    float4 emA = g_emb4[TAIL ? (v0 ? e0 : 0) : e0];
    float4 emB = g_emb4[TAIL ? (v1 ? e1 : 0) : e1];

    u64 eA0 = pack2(emA.x, emA.x), eA1 = pack2(emA.y, emA.y), eA2 = pack2(emA.z, emA.z);
    u64 eB0 = pack2(emB.x, emB.x), eB1 = pack2(emB.y, emB.y), eB2 = pack2(emB.z, emB.z);

    u64 accA[4], accB[4];
#pragma unroll
    for (int j = 0; j < 4; j++) { accA[j] = 0ull; accB[j] = 0ull; }

#pragma unroll
    for (int kp = 0; kp < 8; kp++) {
        R_PAIRS(cw.w1[4], kp)
        const u64x2* wr0 = (const u64x2*)&cw.m[(2 * kp) * 4];
        const u64x2* wr1 = (const u64x2*)&cw.m[(2 * kp + 1) * 4];
#pragma unroll
        for (int q = 0; q < 2; q++) {
            u64x2 w = wr0[q];
            fma2(accA[2 * q], raA, w.x); fma2(accA[2 * q + 1], raA, w.y);
            fma2(accB[2 * q], raB, w.x); fma2(accB[2 * q + 1], raB, w.y);
        }
#pragma unroll
        for (int q = 0; q < 2; q++) {
            u64x2 w = wr1[q];
            fma2(accA[2 * q], rbA, w.x); fma2(accA[2 * q + 1], rbA, w.y);
            fma2(accB[2 * q], rbB, w.x); fma2(accB[2 * q + 1], rbB, w.y);
        }
    }

    {
        u64 xu0 = pack2(x0.x, x0.x), xu1 = pack2(x0.y, x0.y);
        u64 xu2 = pack2(x0.z, x0.z), xu3 = pack2(x0.w, x0.w);
        u64 mc = mul2(xu0, accA[0]);
        fma2(mc, xu1, accA[1]); fma2(mc, xu2, accA[2]); fma2(mc, xu3, accA[3]);
        float m0, m1;
        unpack2(mc, m0, m1);
        if (v0) red_add_v2(out + 2 * d0, m0, m1);
    }
    {
        u64 xu0 = pack2(x1.x, x1.x), xu1 = pack2(x1.y, x1.y);
        u64 xu2 = pack2(x1.z, x1.z), xu3 = pack2(x1.w, x1.w);
        u64 mc = mul2(xu0, accB[0]);
        fma2(mc, xu1, accB[1]); fma2(mc, xu2, accB[2]); fma2(mc, xu3, accB[3]);
        float m0, m1;
        unpack2(mc, m0, m1);
        if (v1) red_add_v2(out + 2 * d1, m0, m1);
    }
}

__global__ void __launch_bounds__(128, 8) conv3_kernel(
    const int* __restrict__ esrc, const int* __restrict__ edst,
    const float4* __restrict__ xin, float* __restrict__ out, int E)
{
    int t = threadIdx.x;
    int base = blockIdx.x * 256;
    if (base + 256 <= E) conv3_body<false>(esrc, edst, xin, out, base, t, E);
    else                 conv3_body<true >(esrc, edst, xin, out, base, t, E);
}

// ============================================================================
extern "C" void kernel_launch(void* const* d_in, const int* in_sizes, int n_in,
                              void* d_out, int out_size)
{
    const float* pos     = (const float*)d_in[0];
    const float* feat    = (const float*)d_in[1];
    const int*   esrc    = (const int*)  d_in[2];
    const int*   edst    = (const int*)  d_in[3];
    const float* fc1_w1  = (const float*)d_in[4];
    const float* fc1_w2  = (const float*)d_in[5];
    const float* core_w1 = (const float*)d_in[6];   // [3,3,16]
    const float* core_w2 = (const float*)d_in[7];   // [3,16,48]
    const float* fc3_w1  = (const float*)d_in[8];
    const float* fc3_w2  = (const float*)d_in[9];
    const float* conv_w  = (const float*)d_in[10];
    const float* conv_b  = (const float*)d_in[11];
    float* out = (float*)d_out;

    int E = in_sizes[2];
    int n = in_sizes[0] / 3;

    float4 *xA, *xB, *xC;
    void* stg;
    cudaGetSymbolAddress((void**)&xA, g_xA);
    cudaGetSymbolAddress((void**)&xB, g_xB);
    cudaGetSymbolAddress((void**)&xC, g_xC);
    cudaGetSymbolAddress(&stg, g_stage);

    int eb = (E + 255) / 256;   // 256 edges per 128-thread block
    int nb = (n + 255) / 256;

    // pack + fold weights, then stage them into the constant bank (D2D, graph-legal)
    wprep_kernel<<<1, 128>>>(fc1_w1, fc1_w2, core_w1, core_w2, fc3_w1, fc3_w2, conv_w);
    cudaMemcpyToSymbolAsync(cw, stg, sizeof(CW), 0, cudaMemcpyDeviceToDevice, 0);

    prep_kernel<<<nb, 256>>>(pos, feat, conv_b, out, n);

    conv1_kernel<<<eb, 128>>>(esrc, edst, xA, E);
    // core1: A->B, zero C for core2's output
    core_kernel<<<eb, 128>>>(esrc, edst, 0, xA, xB, xC, n, E);
    // core2: B->C, zero A for core3's output
    core_kernel<<<eb, 128>>>(esrc, edst, 1, xB, xC, xA, n, E);
    // core3: C->A
    core_kernel<<<eb, 128>>>(esrc, edst, 2, xC, xA, (float4*)0, 0, E);

    conv3_kernel<<<eb, 128>>>(esrc, edst, xA, out, E);
}